// round 3
// baseline (speedup 1.0000x reference)
#include <cuda_runtime.h>
#include <cuda_bf16.h>
#include <cstdint>

// Problem constants
#define T_   64
#define B_   16
#define NT   1024          // T*B tokens
#define D_   512
#define L_   2
#define P_   17            // MULTI_INFER_NUM + 1

// GEMM tiling
#define BM   32            // tokens per tile
#define BN   64            // output dims per tile
#define BK   32            // k chunk
#define TM   4
#define TN   4
#define NTHREADS 128
#define MAX_TILES 64       // upper bound on sum ceil(cnt_p/32) (<= 49)

// ---------------- device scratch (no allocations allowed) ----------------
__device__ int   g_token_idx[NT];
__device__ int   g_tile_bucket[MAX_TILES];
__device__ int   g_tile_row[MAX_TILES];
__device__ int   g_tile_nrows[MAX_TILES];
__device__ int   g_num_tiles;
__device__ float g_mid[NT * D_];   // layer-1 output ping buffer (2 MB)

// ---------------- bucket list construction ----------------
__global__ void build_lists_kernel(const int* __restrict__ positions) {
    __shared__ int cnt[P_];
    __shared__ int off[P_ + 1];
    const int tid = threadIdx.x;          // 0..1023, one per token
    if (tid < P_) cnt[tid] = 0;
    __syncthreads();
    int r = positions[tid];
    r = (r < 16) ? r : 16;
    int rank = atomicAdd(&cnt[r], 1);
    __syncthreads();
    if (tid == 0) {
        int s = 0;
        for (int p = 0; p < P_; p++) { off[p] = s; s += cnt[p]; }
        off[P_] = s;
        int nt = 0;
        for (int p = 0; p < P_; p++) {
            for (int row = 0; row < cnt[p]; row += BM) {
                g_tile_bucket[nt] = p;
                g_tile_row[nt]    = off[p] + row;
                int rem = cnt[p] - row;
                g_tile_nrows[nt]  = rem < BM ? rem : BM;
                nt++;
            }
        }
        g_num_tiles = nt;
    }
    __syncthreads();
    g_token_idx[off[r] + rank] = tid;
}

// ---------------- fused per-layer GEMM + gating ----------------
__device__ __forceinline__ float sigm_f(float v) {
    return 1.f / (1.f + __expf(-v));
}
__device__ __forceinline__ float tanh_f(float v) {
    return 2.f / (1.f + __expf(-2.f * v)) - 1.f;
}

__global__ void __launch_bounds__(NTHREADS, 2)
layer_kernel(const float* __restrict__ x_ext_in,
             float* __restrict__ x_ext_out,
             const float* __restrict__ Ws_l,   // [4][P][D][D] for this layer
             const float* __restrict__ bs_l,   // [4][P][D]    for this layer
             int in_is_mid, int out_is_mid)
{
    const float* x_in  = in_is_mid  ? g_mid : x_ext_in;
    float*       x_out = out_is_mid ? g_mid : x_ext_out;

    const int tile = blockIdx.x;
    if (tile >= g_num_tiles) return;
    const int p     = g_tile_bucket[tile];
    const int row0  = g_tile_row[tile];
    const int nrows = g_tile_nrows[tile];
    const int n0    = blockIdx.y * BN;

    __shared__ float Xs[BK][BM + 1];       // padded: conflict-free stores
    __shared__ float Wsm[4][BK][BN];
    __shared__ int   toks[BM];

    const int tid = threadIdx.x;
    const int tx  = tid & 15;    // col group  (16 groups * TN=4 -> BN=64)
    const int ty  = tid >> 4;    // token group (8 groups * TM=4 -> BM=32)

    if (tid < BM) {
        int m  = tid;
        int mm = (m < nrows) ? m : (nrows - 1);   // clamp dummy rows
        toks[m] = g_token_idx[row0 + mm];
    }
    __syncthreads();

    float acc[4][TM][TN];
#pragma unroll
    for (int j = 0; j < 4; j++)
#pragma unroll
        for (int i = 0; i < TM; i++)
#pragma unroll
            for (int c = 0; c < TN; c++) acc[j][i][c] = 0.f;

    const float* Wb[4];
#pragma unroll
    for (int j = 0; j < 4; j++)
        Wb[j] = Ws_l + ((size_t)j * P_ + p) * (size_t)(D_ * D_) + n0;

    for (int k0 = 0; k0 < D_; k0 += BK) {
        // --- load X tile: BK*BM = 1024 floats, coalesced 128B rows ---
#pragma unroll
        for (int i = 0; i < (BK * BM) / NTHREADS; i++) {
            int flat = tid + i * NTHREADS;
            int k = flat & (BK - 1);
            int m = flat >> 5;                       // BK == 32
            Xs[k][m] = x_in[(size_t)toks[m] * D_ + k0 + k];
        }
        // --- load W tiles: 4*BK*BN floats = 2048 float4 ---
#pragma unroll
        for (int i = 0; i < 16; i++) {
            int flat = tid + i * NTHREADS;           // 0..2047
            int c4 = flat & 15;
            int k  = (flat >> 4) & (BK - 1);
            int j  = flat >> 9;
            float4 v = *reinterpret_cast<const float4*>(
                Wb[j] + (size_t)(k0 + k) * D_ + c4 * 4);
            *reinterpret_cast<float4*>(&Wsm[j][k][c4 * 4]) = v;
        }
        __syncthreads();

#pragma unroll
        for (int k = 0; k < BK; k++) {
            float xf[TM];
#pragma unroll
            for (int i = 0; i < TM; i++) xf[i] = Xs[k][ty * TM + i];
#pragma unroll
            for (int j = 0; j < 4; j++) {
                float4 w = *reinterpret_cast<const float4*>(&Wsm[j][k][tx * TN]);
#pragma unroll
                for (int i = 0; i < TM; i++) {
                    acc[j][i][0] += xf[i] * w.x;
                    acc[j][i][1] += xf[i] * w.y;
                    acc[j][i][2] += xf[i] * w.z;
                    acc[j][i][3] += xf[i] * w.w;
                }
            }
        }
        __syncthreads();
    }

    // --- epilogue: bias + gated combine, scatter to output rows ---
    float bias[4][TN];
#pragma unroll
    for (int j = 0; j < 4; j++) {
        float4 bv = *reinterpret_cast<const float4*>(
            bs_l + ((size_t)j * P_ + p) * D_ + n0 + tx * TN);
        bias[j][0] = bv.x; bias[j][1] = bv.y; bias[j][2] = bv.z; bias[j][3] = bv.w;
    }

#pragma unroll
    for (int i = 0; i < TM; i++) {
        int m = ty * TM + i;
        if (m < nrows) {
            int tok = toks[m];
            float4 xv = *reinterpret_cast<const float4*>(
                x_in + (size_t)tok * D_ + n0 + tx * TN);
            float xvc[TN] = {xv.x, xv.y, xv.z, xv.w};
            float outc[TN];
#pragma unroll
            for (int c = 0; c < TN; c++) {
                float sf = acc[0][i][c] + bias[0][c];   // self_forget
                float lg = acc[1][i][c] + bias[1][c];   // logit
                float lf = acc[2][i][c] + bias[2][c];   // logit_forget
                float of = acc[3][i][c] + bias[3][c];   // out_forget
                float nr = xvc[c] * sigm_f(sf) + tanh_f(lg) * sigm_f(lf);
                outc[c]  = tanh_f(nr) * sigm_f(of);
            }
            float4 ov = make_float4(outc[0], outc[1], outc[2], outc[3]);
            *reinterpret_cast<float4*>(
                x_out + (size_t)tok * D_ + n0 + tx * TN) = ov;
        }
    }
}

// ---------------- launch ----------------
extern "C" void kernel_launch(void* const* d_in, const int* in_sizes, int n_in,
                              void* d_out, int out_size)
{
    // Identify inputs by element count (all distinct):
    //   positions: 1024 (int32), outputs: 524288 (f32),
    //   Ws: 35651584 (f32), bs: 69632 (f32)
    const int*   positions = nullptr;
    const float* x0 = nullptr;
    const float* Ws = nullptr;
    const float* bs = nullptr;
    for (int i = 0; i < n_in; i++) {
        switch (in_sizes[i]) {
            case NT:                    positions = (const int*)d_in[i];   break;
            case NT * D_:               x0        = (const float*)d_in[i]; break;
            case L_ * 4 * P_ * D_ * D_: Ws        = (const float*)d_in[i]; break;
            case L_ * 4 * P_ * D_:      bs        = (const float*)d_in[i]; break;
            default: break;
        }
    }
    float* out = (float*)d_out;

    build_lists_kernel<<<1, NT>>>(positions);

    const size_t W_layer_stride = (size_t)4 * P_ * D_ * D_;
    const size_t b_layer_stride = (size_t)4 * P_ * D_;
    dim3 grid(MAX_TILES, D_ / BN);

    // Layer 0: input = x0 (external), output = g_mid
    layer_kernel<<<grid, NTHREADS>>>(x0, out, Ws, bs,
                                     /*in_is_mid=*/0, /*out_is_mid=*/1);
    // Layer 1: input = g_mid, output = d_out
    layer_kernel<<<grid, NTHREADS>>>(x0, out,
                                     Ws + W_layer_stride, bs + b_layer_stride,
                                     /*in_is_mid=*/1, /*out_is_mid=*/0);
    (void)out_size;
}

// round 5
// speedup vs baseline: 3.3720x; 3.3720x over previous
#include <cuda_runtime.h>
#include <cuda_fp16.h>
#include <cstdint>

// ---------------- problem constants ----------------
#define NT   1024          // T*B tokens
#define D_   512
#define L_   2
#define P_   17            // MULTI_INFER_NUM + 1

// ---------------- tiling ----------------
#define BM        32       // tokens per m-tile
#define BN        64       // output cols per gate per CTA (x4 gates = 256 N)
#define KC        32       // k chunk per stage
#define NCH       (D_/KC)  // 16 chunks
#define MAX_TILES 50       // sum ceil(cnt_p/32) <= 32 + 17 = 49
#define NTH       256      // 8 warps

// smem byte strides (padded for conflict-free ldmatrix, no XOR swizzle)
#define A_STRIDE  80       // 32 halfs(64B) padded to 80B: m-row stride
#define B_STRIDE  528      // 256 halfs(512B) padded to 528B: k-row stride
#define ASZ       (BM * A_STRIDE)     // 2560
#define BSZ       (KC * B_STRIDE)     // 16896
#define OFF_A0    0
#define OFF_A1    ASZ
#define OFF_B0    (2 * ASZ)
#define OFF_B1    (2 * ASZ + BSZ)
#define STAGE_BYTES (2 * ASZ + 2 * BSZ)   // 38912
#define EPI_STRIDE 65                     // fp32 cols incl. pad; 4*32*65*4 = 33280 <= STAGE_BYTES

// ---------------- device scratch ----------------
__device__ int   g_token_idx[NT];
__device__ int   g_tile_bucket[MAX_TILES];
__device__ int   g_tile_row[MAX_TILES];
__device__ int   g_tile_nrows[MAX_TILES];
__device__ int   g_num_tiles;
__device__ float g_mid[NT * D_];     // layer-0 output ping buffer (2 MB)

// ---------------- helpers ----------------
__device__ __forceinline__ uint32_t smem_u32(const void* p) {
    uint32_t a;
    asm("{ .reg .u64 t; cvta.to.shared.u64 t, %1; cvt.u32.u64 %0, t; }" : "=r"(a) : "l"(p));
    return a;
}
__device__ __forceinline__ uint32_t pk2(float a, float b) {
    __half2 h = __floats2half2_rn(a, b);
    return *reinterpret_cast<uint32_t*>(&h);
}
__device__ __forceinline__ void ldsm_x4(uint32_t* r, uint32_t addr) {
    asm volatile("ldmatrix.sync.aligned.m8n8.x4.shared.b16 {%0,%1,%2,%3}, [%4];"
                 : "=r"(r[0]), "=r"(r[1]), "=r"(r[2]), "=r"(r[3]) : "r"(addr));
}
__device__ __forceinline__ void ldsm_x4_t(uint32_t* r, uint32_t addr) {
    asm volatile("ldmatrix.sync.aligned.m8n8.x4.trans.shared.b16 {%0,%1,%2,%3}, [%4];"
                 : "=r"(r[0]), "=r"(r[1]), "=r"(r[2]), "=r"(r[3]) : "r"(addr));
}
__device__ __forceinline__ void mma16816(float* c, const uint32_t* a, uint32_t b0, uint32_t b1) {
    asm volatile(
        "mma.sync.aligned.m16n8k16.row.col.f32.f16.f16.f32 "
        "{%0,%1,%2,%3}, {%4,%5,%6,%7}, {%8,%9}, {%0,%1,%2,%3};"
        : "+f"(c[0]), "+f"(c[1]), "+f"(c[2]), "+f"(c[3])
        : "r"(a[0]), "r"(a[1]), "r"(a[2]), "r"(a[3]), "r"(b0), "r"(b1));
}
__device__ __forceinline__ float sigm_f(float v) { return 1.f / (1.f + __expf(-v)); }
__device__ __forceinline__ float tanh_f(float v) { return 2.f / (1.f + __expf(-2.f * v)) - 1.f; }

// ---------------- bucket list construction ----------------
__global__ void build_lists_kernel(const int* __restrict__ positions) {
    __shared__ int cnt[P_];
    __shared__ int off[P_ + 1];
    const int tid = threadIdx.x;          // one thread per token
    if (tid < P_) cnt[tid] = 0;
    __syncthreads();
    int r = positions[tid];
    r = (r < 16) ? r : 16;
    int rank = atomicAdd(&cnt[r], 1);
    __syncthreads();
    if (tid == 0) {
        int s = 0;
        for (int p = 0; p < P_; p++) { off[p] = s; s += cnt[p]; }
        off[P_] = s;
        int nt = 0;
        for (int p = 0; p < P_; p++) {
            for (int row = 0; row < cnt[p]; row += BM) {
                g_tile_bucket[nt] = p;
                g_tile_row[nt]    = off[p] + row;
                int rem = cnt[p] - row;
                g_tile_nrows[nt]  = rem < BM ? rem : BM;
                nt++;
            }
        }
        g_num_tiles = nt;
    }
    __syncthreads();
    g_token_idx[off[r] + rank] = tid;
}

// ---------------- fused per-layer HMMA GEMM + gating ----------------
__global__ void __launch_bounds__(NTH, 2)
layer_kernel(const float* __restrict__ x_ext_in,
             float* __restrict__ x_ext_out,
             const float* __restrict__ Ws_l,   // [4][P][D][D] fp32 for this layer
             const float* __restrict__ bs_l,   // [4][P][D]
             int in_is_mid, int out_is_mid)
{
    __shared__ __align__(16) char smem[STAGE_BYTES];
    __shared__ int   toks[BM];
    __shared__ float bias_sm[4 * BN];

    const float* x_in  = in_is_mid  ? g_mid : x_ext_in;
    float*       x_out = out_is_mid ? g_mid : x_ext_out;

    const int tile = blockIdx.x;
    if (tile >= g_num_tiles) return;
    const int p     = g_tile_bucket[tile];
    const int row0  = g_tile_row[tile];
    const int nrows = g_tile_nrows[tile];
    const int n0    = blockIdx.y * BN;

    const int tid  = threadIdx.x;
    const int wid  = tid >> 5;
    const int lane = tid & 31;

    if (tid < BM) {
        int mm = (tid < nrows) ? tid : (nrows - 1);
        toks[tid] = g_token_idx[row0 + mm];
    }
    {   // all 256 threads: one bias element each
        int j = tid >> 6, c = tid & 63;
        bias_sm[tid] = bs_l[((size_t)j * P_ + p) * D_ + n0 + c];
    }
    __syncthreads();

    const uint32_t sb = smem_u32(smem);

    // ---- per-thread staging setup ----
    // B: 4 units/thread; unit idx = tid + i*256 over 1024: k=idx>>5, nc=idx&31
    //    gate j = nc>>3, col = (nc&7)*8  -> gmem W[j][p][k][n0+col..+7]
    const float* bsrc[4];
    uint32_t     bsts[4];
#pragma unroll
    for (int i = 0; i < 4; i++) {
        int idx = tid + i * NTH;
        int k = idx >> 5, nc = idx & 31;
        int j = nc >> 3, col = (nc & 7) * 8;
        bsrc[i] = Ws_l + ((size_t)j * P_ + p) * (size_t)(D_ * D_) + (size_t)k * D_ + n0 + col;
        bsts[i] = (uint32_t)(k * B_STRIDE + nc * 16);
    }
    // A: threads 0..127: m = tid>>2, kq = tid&3 (8 floats each)
    const float* asrc = nullptr;
    uint32_t     asts = 0;
    if (tid < 128) {
        int m = tid >> 2, kq = tid & 3;
        asrc = x_in + (size_t)toks[m] * D_ + kq * 8;
        asts = (uint32_t)(m * A_STRIDE + kq * 16);
    }

    // prefetch chunk 0
    float4 br[4][2];
    float4 ar[2];
#pragma unroll
    for (int i = 0; i < 4; i++) {
        br[i][0] = *reinterpret_cast<const float4*>(bsrc[i]);
        br[i][1] = *reinterpret_cast<const float4*>(bsrc[i] + 4);
    }
    if (tid < 128) {
        ar[0] = *reinterpret_cast<const float4*>(asrc);
        ar[1] = *reinterpret_cast<const float4*>(asrc + 4);
    }

    // warp tile: gate j_w, n-half within 64-col slice
    const int j_w    = wid >> 1;
    const int nhalf  = (wid & 1) * 32;
    const int ncbase = (j_w * 64 + nhalf) >> 3;     // 16B-chunk base in B rows

    // ldmatrix lane addressing (warp-invariant parts)
    const int a_row  = lane & 15;           // A: row within m16
    const int a_koff = lane >> 4;           // A: which k8 chunk
    const int b_krow = (lane & 7) + ((lane >> 3) & 1) * 8;   // B: k within k16
    const int b_noff = lane >> 4;           // B: +1 chunk (8 cols) for lanes 16-31

    float acc[2][4][4];
#pragma unroll
    for (int mf = 0; mf < 2; mf++)
#pragma unroll
        for (int nf = 0; nf < 4; nf++)
#pragma unroll
            for (int q = 0; q < 4; q++) acc[mf][nf][q] = 0.f;

    for (int s = 0; s < NCH; s++) {
        const uint32_t ab = sb + ((s & 1) ? OFF_A1 : OFF_A0);
        const uint32_t bb = sb + ((s & 1) ? OFF_B1 : OFF_B0);

        // ---- STS staged regs (fp32 -> fp16 pack) ----
#pragma unroll
        for (int i = 0; i < 4; i++) {
            uint4 v;
            v.x = pk2(br[i][0].x, br[i][0].y);
            v.y = pk2(br[i][0].z, br[i][0].w);
            v.z = pk2(br[i][1].x, br[i][1].y);
            v.w = pk2(br[i][1].z, br[i][1].w);
            *reinterpret_cast<uint4*>(smem + (bb - sb) + bsts[i]) = v;
        }
        if (tid < 128) {
            uint4 v;
            v.x = pk2(ar[0].x, ar[0].y);
            v.y = pk2(ar[0].z, ar[0].w);
            v.z = pk2(ar[1].x, ar[1].y);
            v.w = pk2(ar[1].z, ar[1].w);
            *reinterpret_cast<uint4*>(smem + (ab - sb) + asts) = v;
        }
        __syncthreads();

        // ---- prefetch next chunk ----
        if (s + 1 < NCH) {
#pragma unroll
            for (int i = 0; i < 4; i++) {
                bsrc[i] += KC * D_;
                br[i][0] = *reinterpret_cast<const float4*>(bsrc[i]);
                br[i][1] = *reinterpret_cast<const float4*>(bsrc[i] + 4);
            }
            if (tid < 128) {
                asrc += KC;
                ar[0] = *reinterpret_cast<const float4*>(asrc);
                ar[1] = *reinterpret_cast<const float4*>(asrc + 4);
            }
        }

        // ---- compute: 2 k16 steps ----
#pragma unroll
        for (int ks = 0; ks < 2; ks++) {
            uint32_t afr[2][4];
#pragma unroll
            for (int mf = 0; mf < 2; mf++) {
                uint32_t addr = ab + (uint32_t)((mf * 16 + a_row) * A_STRIDE
                                                + (ks * 2 + a_koff) * 16);
                ldsm_x4(afr[mf], addr);
            }
            uint32_t bfr[2][4];
#pragma unroll
            for (int nf2 = 0; nf2 < 2; nf2++) {
                uint32_t addr = bb + (uint32_t)((ks * 16 + b_krow) * B_STRIDE
                                                + (ncbase + nf2 * 2 + b_noff) * 16);
                ldsm_x4_t(bfr[nf2], addr);
            }
#pragma unroll
            for (int mf = 0; mf < 2; mf++)
#pragma unroll
                for (int nf = 0; nf < 4; nf++) {
                    int nf2 = nf >> 1, sel = (nf & 1) * 2;
                    mma16816(acc[mf][nf], afr[mf], bfr[nf2][sel], bfr[nf2][sel + 1]);
                }
        }
    }

    // ---- epilogue: exchange gate accumulators through smem, fuse gating ----
    __syncthreads();                       // everyone done reading stage buffers
    float* epi = reinterpret_cast<float*>(smem);     // [4][32][EPI_STRIDE]

#pragma unroll
    for (int mf = 0; mf < 2; mf++)
#pragma unroll
        for (int nf = 0; nf < 4; nf++) {
            int r = mf * 16 + (lane >> 2);
            int c = nhalf + nf * 8 + (lane & 3) * 2;
            float* e0 = epi + ((j_w * 32 + r) * EPI_STRIDE + c);
            e0[0] = acc[mf][nf][0];
            e0[1] = acc[mf][nf][1];
            float* e1 = epi + ((j_w * 32 + r + 8) * EPI_STRIDE + c);
            e1[0] = acc[mf][nf][2];
            e1[1] = acc[mf][nf][3];
        }
    __syncthreads();

#pragma unroll
    for (int i = 0; i < 8; i++) {
        int flat = tid + i * NTH;          // 0..2047 = 32m x 64c
        int m = flat >> 6, c = flat & 63;
        if (m < nrows) {
            int tok = toks[m];
            float sf = epi[(0 * 32 + m) * EPI_STRIDE + c] + bias_sm[0 * 64 + c];
            float lg = epi[(1 * 32 + m) * EPI_STRIDE + c] + bias_sm[1 * 64 + c];
            float lf = epi[(2 * 32 + m) * EPI_STRIDE + c] + bias_sm[2 * 64 + c];
            float of = epi[(3 * 32 + m) * EPI_STRIDE + c] + bias_sm[3 * 64 + c];
            float xv = x_in[(size_t)tok * D_ + n0 + c];
            float nr = xv * sigm_f(sf) + tanh_f(lg) * sigm_f(lf);
            x_out[(size_t)tok * D_ + n0 + c] = tanh_f(nr) * sigm_f(of);
        }
    }
}

// ---------------- launch ----------------
extern "C" void kernel_launch(void* const* d_in, const int* in_sizes, int n_in,
                              void* d_out, int out_size)
{
    const int*   positions = nullptr;
    const float* x0 = nullptr;
    const float* Ws = nullptr;
    const float* bs = nullptr;
    for (int i = 0; i < n_in; i++) {
        switch (in_sizes[i]) {
            case NT:                    positions = (const int*)d_in[i];   break;
            case NT * D_:               x0        = (const float*)d_in[i]; break;
            case L_ * 4 * P_ * D_ * D_: Ws        = (const float*)d_in[i]; break;
            case L_ * 4 * P_ * D_:      bs        = (const float*)d_in[i]; break;
            default: break;
        }
    }
    float* out = (float*)d_out;

    const size_t W_layer = (size_t)4 * P_ * D_ * D_;
    const size_t b_layer = (size_t)4 * P_ * D_;

    build_lists_kernel<<<1, NT>>>(positions);

    dim3 grid(MAX_TILES, D_ / BN);      // 50 x 8

    // Layer 0: x0 -> g_mid
    layer_kernel<<<grid, NTH>>>(x0, out, Ws, bs, 0, 1);
    // Layer 1: g_mid -> d_out
    layer_kernel<<<grid, NTH>>>(x0, out, Ws + W_layer, bs + b_layer, 1, 0);

    (void)out_size;
}

// round 6
// speedup vs baseline: 4.2661x; 1.2652x over previous
#include <cuda_runtime.h>
#include <cuda_fp16.h>
#include <cstdint>

// ---------------- problem constants ----------------
#define NT   1024          // T*B tokens
#define D_   512
#define L_   2
#define P_   17            // MULTI_INFER_NUM + 1

// ---------------- tiling ----------------
#define BM        48       // tokens per m-tile (3 x m16)
#define BN        64       // output cols per gate per CTA (x4 gates = 256 N)
#define KC        32       // k chunk per stage
#define NCH       (D_/KC)  // 16 chunks
#define MAX_TILES 40       // sum ceil(cnt_p/48) <= 17 + 21 = 38
#define NTH       256      // 8 warps

// smem byte strides (padded, conflict-free ldmatrix without XOR swizzle)
#define A_STRIDE  80       // 32 halfs (64B) padded to 80B per m-row
#define B_STRIDE  528      // 256 halfs (512B) padded to 528B per k-row
#define ASZ       (BM * A_STRIDE)     // 3840
#define BSZ       (KC * B_STRIDE)     // 16896

// dynamic smem layout
#define SM_TOKS   0                   // 48 * 4 = 192
#define SM_BIAS   192                 // 4*64*4 = 1024 -> ends 1216
#define SM_STAGE  1280                // stage buffers / epilogue union
#define OFF_A0    (SM_STAGE)
#define OFF_A1    (SM_STAGE + ASZ)
#define OFF_B0    (SM_STAGE + 2*ASZ)
#define OFF_B1    (SM_STAGE + 2*ASZ + BSZ)
#define EPI_STRIDE 65                 // fp32 cols incl. pad
#define EPI_BYTES (4 * BM * EPI_STRIDE * 4)        // 49920
#define SMEM_TOTAL (SM_STAGE + EPI_BYTES)          // 51200 (> stage end 42752)

// ---------------- device scratch ----------------
__device__ int   g_token_idx[NT];
__device__ int   g_tile_bucket[MAX_TILES];
__device__ int   g_tile_row[MAX_TILES];
__device__ int   g_tile_nrows[MAX_TILES];
__device__ int   g_num_tiles;
__device__ float g_mid[NT * D_];     // layer-0 output ping buffer (2 MB)

// ---------------- helpers ----------------
__device__ __forceinline__ uint32_t smem_u32(const void* p) {
    uint32_t a;
    asm("{ .reg .u64 t; cvta.to.shared.u64 t, %1; cvt.u32.u64 %0, t; }" : "=r"(a) : "l"(p));
    return a;
}
__device__ __forceinline__ uint32_t pk2(float a, float b) {
    __half2 h = __floats2half2_rn(a, b);
    return *reinterpret_cast<uint32_t*>(&h);
}
__device__ __forceinline__ void ldsm_x4(uint32_t* r, uint32_t addr) {
    asm volatile("ldmatrix.sync.aligned.m8n8.x4.shared.b16 {%0,%1,%2,%3}, [%4];"
                 : "=r"(r[0]), "=r"(r[1]), "=r"(r[2]), "=r"(r[3]) : "r"(addr));
}
__device__ __forceinline__ void ldsm_x4_t(uint32_t* r, uint32_t addr) {
    asm volatile("ldmatrix.sync.aligned.m8n8.x4.trans.shared.b16 {%0,%1,%2,%3}, [%4];"
                 : "=r"(r[0]), "=r"(r[1]), "=r"(r[2]), "=r"(r[3]) : "r"(addr));
}
__device__ __forceinline__ void mma16816(float* c, const uint32_t* a, uint32_t b0, uint32_t b1) {
    asm volatile(
        "mma.sync.aligned.m16n8k16.row.col.f32.f16.f16.f32 "
        "{%0,%1,%2,%3}, {%4,%5,%6,%7}, {%8,%9}, {%0,%1,%2,%3};"
        : "+f"(c[0]), "+f"(c[1]), "+f"(c[2]), "+f"(c[3])
        : "r"(a[0]), "r"(a[1]), "r"(a[2]), "r"(a[3]), "r"(b0), "r"(b1));
}
__device__ __forceinline__ float sigm_f(float v) { return 1.f / (1.f + __expf(-v)); }
__device__ __forceinline__ float tanh_f(float v) { return 2.f / (1.f + __expf(-2.f * v)) - 1.f; }

// ---------------- bucket list construction ----------------
__global__ void build_lists_kernel(const int* __restrict__ positions) {
    __shared__ int cnt[P_];
    __shared__ int off[P_ + 1];
    const int tid = threadIdx.x;          // one thread per token
    if (tid < P_) cnt[tid] = 0;
    __syncthreads();
    int r = positions[tid];
    r = (r < 16) ? r : 16;
    int rank = atomicAdd(&cnt[r], 1);
    __syncthreads();
    if (tid == 0) {
        int s = 0;
        for (int p = 0; p < P_; p++) { off[p] = s; s += cnt[p]; }
        off[P_] = s;
        int nt = 0;
        for (int p = 0; p < P_; p++) {
            for (int row = 0; row < cnt[p]; row += BM) {
                g_tile_bucket[nt] = p;
                g_tile_row[nt]    = off[p] + row;
                int rem = cnt[p] - row;
                g_tile_nrows[nt]  = rem < BM ? rem : BM;
                nt++;
            }
        }
        g_num_tiles = nt;
    }
    __syncthreads();
    g_token_idx[off[r] + rank] = tid;
}

// ---------------- fused per-layer HMMA GEMM + gating ----------------
__global__ void __launch_bounds__(NTH, 2)
layer_kernel(const float* __restrict__ x_ext_in,
             float* __restrict__ x_ext_out,
             const float* __restrict__ Ws_l,   // [4][P][D][D] fp32 for this layer
             const float* __restrict__ bs_l,   // [4][P][D]
             int in_is_mid, int out_is_mid)
{
    extern __shared__ __align__(16) char dsm[];
    int*   toks    = reinterpret_cast<int*>(dsm + SM_TOKS);
    float* bias_sm = reinterpret_cast<float*>(dsm + SM_BIAS);

    const float* x_in  = in_is_mid  ? g_mid : x_ext_in;
    float*       x_out = out_is_mid ? g_mid : x_ext_out;

    const int tile = blockIdx.x;
    if (tile >= g_num_tiles) return;
    const int p     = g_tile_bucket[tile];
    const int row0  = g_tile_row[tile];
    const int nrows = g_tile_nrows[tile];
    const int n0    = blockIdx.y * BN;

    const int tid  = threadIdx.x;
    const int wid  = tid >> 5;
    const int lane = tid & 31;

    if (tid < BM) {
        int mm = (tid < nrows) ? tid : (nrows - 1);
        toks[tid] = g_token_idx[row0 + mm];
    }
    {   // 256 threads: one bias element each (4 gates x 64 cols)
        int j = tid >> 6, c = tid & 63;
        bias_sm[tid] = bs_l[((size_t)j * P_ + p) * D_ + n0 + c];
    }
    __syncthreads();

    const uint32_t sb = smem_u32(dsm);

    // ---- per-thread staging setup ----
    // B: 4 units/thread over 1024 units: k=idx>>5, nc=idx&31; gate j=nc>>3, col=(nc&7)*8
    const float* bsrc[4];
    uint32_t     bsts[4];
#pragma unroll
    for (int i = 0; i < 4; i++) {
        int idx = tid + i * NTH;
        int k = idx >> 5, nc = idx & 31;
        int j = nc >> 3, col = (nc & 7) * 8;
        bsrc[i] = Ws_l + ((size_t)j * P_ + p) * (size_t)(D_ * D_) + (size_t)k * D_ + n0 + col;
        bsts[i] = (uint32_t)(k * B_STRIDE + nc * 16);
    }
    // A: threads 0..191: m = tid>>2, kq = tid&3 (8 floats each; 48*32 = 1536 fp32)
    const float* asrc = nullptr;
    uint32_t     asts = 0;
    if (tid < 192) {
        int m = tid >> 2, kq = tid & 3;
        asrc = x_in + (size_t)toks[m] * D_ + kq * 8;
        asts = (uint32_t)(m * A_STRIDE + kq * 16);
    }

    // prefetch chunk 0
    float4 br[4][2];
    float4 ar[2];
#pragma unroll
    for (int i = 0; i < 4; i++) {
        br[i][0] = *reinterpret_cast<const float4*>(bsrc[i]);
        br[i][1] = *reinterpret_cast<const float4*>(bsrc[i] + 4);
    }
    if (tid < 192) {
        ar[0] = *reinterpret_cast<const float4*>(asrc);
        ar[1] = *reinterpret_cast<const float4*>(asrc + 4);
    }

    // warp tile: gate j_w (4), 32-col half within the 64-col slice
    const int j_w    = wid >> 1;
    const int nhalf  = (wid & 1) * 32;
    const int ncbase = (j_w * 64 + nhalf) >> 3;     // 16B-chunk base within B rows

    const int a_row  = lane & 15;
    const int a_koff = lane >> 4;
    const int b_krow = (lane & 7) + ((lane >> 3) & 1) * 8;
    const int b_noff = lane >> 4;

    float acc[3][4][4];
#pragma unroll
    for (int mf = 0; mf < 3; mf++)
#pragma unroll
        for (int nf = 0; nf < 4; nf++)
#pragma unroll
            for (int q = 0; q < 4; q++) acc[mf][nf][q] = 0.f;

    for (int s = 0; s < NCH; s++) {
        const uint32_t aoff = (s & 1) ? OFF_A1 : OFF_A0;
        const uint32_t boff = (s & 1) ? OFF_B1 : OFF_B0;
        const uint32_t ab = sb + aoff;
        const uint32_t bb = sb + boff;

        // ---- STS staged regs (fp32 -> fp16 pack) ----
#pragma unroll
        for (int i = 0; i < 4; i++) {
            uint4 v;
            v.x = pk2(br[i][0].x, br[i][0].y);
            v.y = pk2(br[i][0].z, br[i][0].w);
            v.z = pk2(br[i][1].x, br[i][1].y);
            v.w = pk2(br[i][1].z, br[i][1].w);
            *reinterpret_cast<uint4*>(dsm + boff + bsts[i]) = v;
        }
        if (tid < 192) {
            uint4 v;
            v.x = pk2(ar[0].x, ar[0].y);
            v.y = pk2(ar[0].z, ar[0].w);
            v.z = pk2(ar[1].x, ar[1].y);
            v.w = pk2(ar[1].z, ar[1].w);
            *reinterpret_cast<uint4*>(dsm + aoff + asts) = v;
        }
        __syncthreads();

        // ---- prefetch next chunk ----
        if (s + 1 < NCH) {
#pragma unroll
            for (int i = 0; i < 4; i++) {
                bsrc[i] += KC * D_;
                br[i][0] = *reinterpret_cast<const float4*>(bsrc[i]);
                br[i][1] = *reinterpret_cast<const float4*>(bsrc[i] + 4);
            }
            if (tid < 192) {
                asrc += KC;
                ar[0] = *reinterpret_cast<const float4*>(asrc);
                ar[1] = *reinterpret_cast<const float4*>(asrc + 4);
            }
        }

        // ---- compute: 2 k16 steps ----
#pragma unroll
        for (int ks = 0; ks < 2; ks++) {
            uint32_t afr[3][4];
#pragma unroll
            for (int mf = 0; mf < 3; mf++) {
                uint32_t addr = ab + (uint32_t)((mf * 16 + a_row) * A_STRIDE
                                                + (ks * 2 + a_koff) * 16);
                ldsm_x4(afr[mf], addr);
            }
            uint32_t bfr[2][4];
#pragma unroll
            for (int nf2 = 0; nf2 < 2; nf2++) {
                uint32_t addr = bb + (uint32_t)((ks * 16 + b_krow) * B_STRIDE
                                                + (ncbase + nf2 * 2 + b_noff) * 16);
                ldsm_x4_t(bfr[nf2], addr);
            }
#pragma unroll
            for (int mf = 0; mf < 3; mf++)
#pragma unroll
                for (int nf = 0; nf < 4; nf++) {
                    int nf2 = nf >> 1, sel = (nf & 1) * 2;
                    mma16816(acc[mf][nf], afr[mf], bfr[nf2][sel], bfr[nf2][sel + 1]);
                }
        }
    }

    // ---- epilogue: exchange gate accumulators through smem, fuse gating ----
    __syncthreads();                       // stage buffers free -> reuse as epi
    float* epi = reinterpret_cast<float*>(dsm + SM_STAGE);     // [4][BM][EPI_STRIDE]

#pragma unroll
    for (int mf = 0; mf < 3; mf++)
#pragma unroll
        for (int nf = 0; nf < 4; nf++) {
            int r = mf * 16 + (lane >> 2);
            int c = nhalf + nf * 8 + (lane & 3) * 2;
            float* e0 = epi + ((j_w * BM + r) * EPI_STRIDE + c);
            e0[0] = acc[mf][nf][0];
            e0[1] = acc[mf][nf][1];
            float* e1 = epi + ((j_w * BM + r + 8) * EPI_STRIDE + c);
            e1[0] = acc[mf][nf][2];
            e1[1] = acc[mf][nf][3];
        }
    __syncthreads();

#pragma unroll
    for (int i = 0; i < (BM * 64) / NTH; i++) {     // 12 iterations
        int flat = tid + i * NTH;          // 0..3071 = 48m x 64c
        int m = flat >> 6, c = flat & 63;
        if (m < nrows) {
            int tok = toks[m];
            float sf = epi[(0 * BM + m) * EPI_STRIDE + c] + bias_sm[0 * 64 + c];
            float lg = epi[(1 * BM + m) * EPI_STRIDE + c] + bias_sm[1 * 64 + c];
            float lf = epi[(2 * BM + m) * EPI_STRIDE + c] + bias_sm[2 * 64 + c];
            float of = epi[(3 * BM + m) * EPI_STRIDE + c] + bias_sm[3 * 64 + c];
            float xv = x_in[(size_t)tok * D_ + n0 + c];
            float nr = xv * sigm_f(sf) + tanh_f(lg) * sigm_f(lf);
            x_out[(size_t)tok * D_ + n0 + c] = tanh_f(nr) * sigm_f(of);
        }
    }
}

// ---------------- launch ----------------
extern "C" void kernel_launch(void* const* d_in, const int* in_sizes, int n_in,
                              void* d_out, int out_size)
{
    const int*   positions = nullptr;
    const float* x0 = nullptr;
    const float* Ws = nullptr;
    const float* bs = nullptr;
    for (int i = 0; i < n_in; i++) {
        switch (in_sizes[i]) {
            case NT:                    positions = (const int*)d_in[i];   break;
            case NT * D_:               x0        = (const float*)d_in[i]; break;
            case L_ * 4 * P_ * D_ * D_: Ws        = (const float*)d_in[i]; break;
            case L_ * 4 * P_ * D_:      bs        = (const float*)d_in[i]; break;
            default: break;
        }
    }
    float* out = (float*)d_out;

    cudaFuncSetAttribute(layer_kernel,
                         cudaFuncAttributeMaxDynamicSharedMemorySize, SMEM_TOTAL);

    const size_t W_layer = (size_t)4 * P_ * D_ * D_;
    const size_t b_layer = (size_t)4 * P_ * D_;

    build_lists_kernel<<<1, NT>>>(positions);

    dim3 grid(MAX_TILES, D_ / BN);      // 40 x 8 (real tiles ~27 -> ~216 live CTAs)

    // Layer 0: x0 -> g_mid
    layer_kernel<<<grid, NTH, SMEM_TOTAL>>>(x0, out, Ws, bs, 0, 1);
    // Layer 1: g_mid -> d_out
    layer_kernel<<<grid, NTH, SMEM_TOTAL>>>(x0, out, Ws + W_layer, bs + b_layer, 1, 0);

    (void)out_size;
}